// round 12
// baseline (speedup 1.0000x reference)
#include <cuda_runtime.h>
#include <cuda_bf16.h>
#include <stdint.h>

// Inputs (metadata order):
//   d_in[0]: inputs_t  int32  [1, n_source]   (n_source = 17400)
//   d_in[1]: indices   int32  [N_SYN, 2]  -> (post, pre) per row
//   d_in[2]: weights   float32 [N_SYN]
//   d_in[3]: n_post    (scalar; we use out_size instead)
// Output: float32 [1, n_post]
//
// Model (rounds 2-11): scatter pinned at ~106us by the L2/LTS op wall
// (11.25M stream-read sectors + ~15M predicated RED.ADD.F32). This round:
// mark the zero-reuse idx/weight stream loads cache-streaming (__ldcs,
// evict-first) so the hot 69.6KB activity table stays L1-resident and its
// gathers stop spilling extra ops onto the LTS wall.

// 4 synapses per thread: two int4 index loads + one float4 weight load.
__global__ void __launch_bounds__(256) scatter4_kernel(
    const int*    __restrict__ act,    // inputs_t, n_source ints (L1-resident)
    const int4*   __restrict__ idx4,   // (post0,pre0,post1,pre1) pairs
    const float4* __restrict__ w4,
    float*        __restrict__ out,
    int n_quads)                        // n_syn / 4
{
    int i = blockIdx.x * blockDim.x + threadIdx.x;
    if (i >= n_quads) return;

    // Streaming loads: evict-first, keep L1 for the act table.
    int4   a  = __ldcs(idx4 + 2 * i);
    int4   b  = __ldcs(idx4 + 2 * i + 1);
    float4 wv = __ldcs(w4 + i);

    // Front-batch the gather loads so all four are in flight before any RED.
    int act0 = __ldg(act + a.y);
    int act1 = __ldg(act + a.w);
    int act2 = __ldg(act + b.y);
    int act3 = __ldg(act + b.w);

    if (act0 > 0) atomicAdd(out + a.x, wv.x);
    if (act1 > 0) atomicAdd(out + a.z, wv.y);
    if (act2 > 0) atomicAdd(out + b.x, wv.z);
    if (act3 > 0) atomicAdd(out + b.z, wv.w);
}

// Tail for n_syn not divisible by 4 (not launched for N_SYN=30M).
__global__ void scatter_tail_kernel(
    const int*  __restrict__ act,
    const int2* __restrict__ idx2,
    const float* __restrict__ w,
    float*       __restrict__ out,
    int start, int n_syn)
{
    int i = start + blockIdx.x * blockDim.x + threadIdx.x;
    if (i >= n_syn) return;
    int2 p = __ldcs(idx2 + i);
    if (__ldg(act + p.y) > 0) atomicAdd(out + p.x, __ldcs(w + i));
}

extern "C" void kernel_launch(void* const* d_in, const int* in_sizes, int n_in,
                              void* d_out, int out_size) {
    const int*   act     = (const int*)d_in[0];
    const int*   indices = (const int*)d_in[1];
    const float* weights = (const float*)d_in[2];
    float*       out     = (float*)d_out;

    const int n_syn = in_sizes[2];   // weights element count

    // Zero the output with a memset node (graph-capturable, no SM launch).
    cudaMemsetAsync(out, 0, (size_t)out_size * sizeof(float), 0);

    const int n_quads = n_syn / 4;
    if (n_quads > 0) {
        int threads = 256;
        int blocks  = (n_quads + threads - 1) / threads;
        scatter4_kernel<<<blocks, threads>>>(
            act, (const int4*)indices, (const float4*)weights, out, n_quads);
    }

    const int done = n_quads * 4;
    if (done < n_syn) {           // not taken for n_syn = 30M
        int rem = n_syn - done;
        int threads = 256;
        int blocks  = (rem + threads - 1) / threads;
        scatter_tail_kernel<<<blocks, threads>>>(
            act, (const int2*)indices, weights, out, done, n_syn);
    }
}